// round 12
// baseline (speedup 1.0000x reference)
#include <cuda_runtime.h>
#include <cuda_fp16.h>
#include <cstdint>

// Problem constants (fixed by the dataset):
//   N = 50000 nodes, C = 128 channels, E = 400000 edges,
//   T = 12 edge types, P = 16 (4x4 restriction map)
// Y layout per node: [half(src=0/dst=1)][t][p]  -> 2*12*16 = 384 cols
#define NMAX   50000
#define CDIM   128
#define NCOLS  384

// Scratch (allocation-free rule: __device__ globals)
__device__ __half g_Bh[NCOLS * CDIM];                // 96 KB, fp16 W^T: [n][k]
__device__ __half g_Yh[(size_t)NMAX * NCOLS];        // 38.4 MB, fp16 node partials

__device__ __forceinline__ uint32_t smem_u32(const void* p) {
    return (uint32_t)__cvta_generic_to_shared(p);
}
__device__ __forceinline__ void cp_async16(void* smem_dst, const void* gsrc) {
    asm volatile("cp.async.ca.shared.global [%0], [%1], 16;\n"
                 :: "r"(smem_u32(smem_dst)), "l"(gsrc));
}
#define CP_COMMIT() asm volatile("cp.async.commit_group;\n" ::)
#define CP_WAIT0()  asm volatile("cp.async.wait_group 0;\n" ::)

__device__ __forceinline__ void ldsm_x4(uint32_t& r0, uint32_t& r1,
                                        uint32_t& r2, uint32_t& r3,
                                        uint32_t addr) {
    asm volatile("ldmatrix.sync.aligned.m8n8.x4.shared.b16 {%0,%1,%2,%3}, [%4];"
                 : "=r"(r0), "=r"(r1), "=r"(r2), "=r"(r3) : "r"(addr));
}

__device__ __forceinline__ float fast_tanh(float x) {
    float y;
    asm("tanh.approx.f32 %0, %1;" : "=f"(y) : "f"(x));
    return y;
}

// ---------------------------------------------------------------------------
// Kernel 1: prep — coalesced read of W, scattered fp16 write.
// Thread i reads W[i]; i = ((t*256 + row)*16 + p), row = half*128 + c;
// writes g_Bh[n*128 + c] with n = half*192 + t*16 + p.
// ---------------------------------------------------------------------------
__global__ void prep_kernel(const float* __restrict__ W) {
    int i = blockIdx.x * blockDim.x + threadIdx.x;   // 0 .. 49151
    float w = W[i];
    int p   = i & 15;
    int row = (i >> 4) & 255;
    int t   = i >> 12;
    int half = row >> 7;
    int c    = row & 127;
    int n    = half * 192 + t * 16 + p;
    g_Bh[n * CDIM + c] = __float2half_rn(w);
}

// ---------------------------------------------------------------------------
// Kernel 2: Y[M,384] = fp16(X[M,128]) @ Bh^T, fp32 accumulate, fp16 out.
// CTA tile 128(M) x 128(N); K chunked 4 x 32, DOUBLE-BUFFERED:
//   B chunks via cp.async; A chunks via LDG f32 -> register staging -> cvt ->
//   STS, issued so chunk k+1's global traffic overlaps compute(k).
// One __syncthreads per chunk. Static smem: 4 buffers of 128x40 halves
// (A0,A1,B0,B1) = 40 KB < 48 KB -> no opt-in attr needed.
// 8 warps in 4(M) x 2(N); warp tile 32x64 via ldmatrix.x4 + mma.m16n8k16.
// SPAD=40 halves (80 B rows): LDSM 8-row phases hit bank groups
// {0,20,8,28,16,4,24,12} (x4 banks) = all 32 banks once -> conflict-free.
// ---------------------------------------------------------------------------
#define KC        32
#define NCHUNK    (CDIM / KC)
#define SPAD      40
#define BUF_ELEMS (128 * SPAD)       // 5120 halves = 10240 B per buffer

__global__ void __launch_bounds__(256, 2)
gemm_kernel(const float* __restrict__ X, int M) {
    __shared__ __half smem[4 * BUF_ELEMS];   // A0 A1 B0 B1
    __half* Abuf[2] = { smem,                 smem + BUF_ELEMS };
    __half* Bbuf[2] = { smem + 2 * BUF_ELEMS, smem + 3 * BUF_ELEMS };

    const int m0  = blockIdx.x * 128;
    const int n0  = blockIdx.y * 128;
    const int tid = threadIdx.x;

    // Per-thread load coordinates
    const int ar = tid >> 1;                 // A row pair-id: li = tid + i*256
    (void)ar;
    // A: 1024 float4 per chunk -> 4 per thread: li = tid + i*256,
    //    r = li>>3 (0..127), c4 = (li&7)*4 (f32 col in chunk)
    // B: 512 cp16 per chunk -> 2 per thread: li = tid + i*256,
    //    r = li>>2 (0..127), c = (li&3)*8 (half col in chunk)

    // A register staging for the in-flight chunk
    float4 a_stage[4];

    auto ldg_A = [&](int kc) {
        const int kc0 = kc * KC;
        #pragma unroll
        for (int i = 0; i < 4; ++i) {
            int li = tid + i * 256;
            int r  = li >> 3;
            int c4 = (li & 7) << 2;
            float4 v = make_float4(0.f, 0.f, 0.f, 0.f);
            if (m0 + r < M)
                v = *reinterpret_cast<const float4*>(
                        X + (size_t)(m0 + r) * CDIM + kc0 + c4);
            a_stage[i] = v;
        }
    };
    auto sts_A = [&](int buf) {
        #pragma unroll
        for (int i = 0; i < 4; ++i) {
            int li = tid + i * 256;
            int r  = li >> 3;
            int c4 = (li & 7) << 2;
            __half2 h0 = __floats2half2_rn(a_stage[i].x, a_stage[i].y);
            __half2 h1 = __floats2half2_rn(a_stage[i].z, a_stage[i].w);
            uint2 u;
            u.x = *reinterpret_cast<uint32_t*>(&h0);
            u.y = *reinterpret_cast<uint32_t*>(&h1);
            *reinterpret_cast<uint2*>(Abuf[buf] + r * SPAD + c4) = u;
        }
    };
    auto cp_B = [&](int kc, int buf) {
        const int kc0 = kc * KC;
        #pragma unroll
        for (int i = 0; i < 2; ++i) {
            int li = tid + i * 256;
            int r  = li >> 2;
            int c  = (li & 3) << 3;
            cp_async16(Bbuf[buf] + r * SPAD + c,
                       g_Bh + (size_t)(n0 + r) * CDIM + kc0 + c);
        }
    };

    const int warp = tid >> 5;
    const int lane = tid & 31;
    const int wm   = warp >> 1;   // 0..3
    const int wn   = warp & 1;    // 0..1
    const int mat  = lane >> 3;
    const int mrl  = lane & 7;

    // ldmatrix base addresses for buffer 0; buffer 1 = +BUF_ELEMS*2 bytes.
    uint32_t a_base[2];
    #pragma unroll
    for (int mt = 0; mt < 2; ++mt) {
        int row = wm * 32 + mt * 16 + (mat & 1) * 8 + mrl;
        int col = (mat >> 1) * 8;
        a_base[mt] = smem_u32(Abuf[0] + row * SPAD + col);
    }
    uint32_t b_base[4];
    #pragma unroll
    for (int g = 0; g < 4; ++g) {
        int row = wn * 64 + (2 * g + (mat >> 1)) * 8 + mrl;
        int col = (mat & 1) * 8;
        b_base[g] = smem_u32(Bbuf[0] + row * SPAD + col);
    }
    const uint32_t BUFB = BUF_ELEMS * 2;   // byte offset between buffers

    float acc[2][8][4];
    #pragma unroll
    for (int mt = 0; mt < 2; ++mt)
        #pragma unroll
        for (int nt = 0; nt < 8; ++nt)
            #pragma unroll
            for (int q = 0; q < 4; ++q)
                acc[mt][nt][q] = 0.f;

    // ---- Pipeline prologue: chunk 0 traffic in flight ----
    ldg_A(0);
    cp_B(0, 0);
    CP_COMMIT();

    #pragma unroll
    for (int kc = 0; kc < NCHUNK; ++kc) {
        const int buf = kc & 1;
        sts_A(buf);                    // regs -> Abuf[buf] (WAR-safe: buf was
                                       // retired by sync of iteration kc-1)
        if (kc + 1 < NCHUNK)
            ldg_A(kc + 1);             // overlap next A LDG with wait+compute
        CP_WAIT0();                    // B[kc] landed (only group outstanding)
        __syncthreads();               // STS + B visible; compute(kc-1) retired
        if (kc + 1 < NCHUNK) {
            cp_B(kc + 1, buf ^ 1);     // safe: buf^1 compute retired by sync
            CP_COMMIT();
        }

        const uint32_t bo = buf ? BUFB : 0;
        #pragma unroll
        for (int ks = 0; ks < 2; ++ks) {          // 2 k16 steps per chunk
            const uint32_t koff = bo + ks * 32;   // 16 halves = 32 B
            uint32_t a[2][4];
            #pragma unroll
            for (int mt = 0; mt < 2; ++mt)
                ldsm_x4(a[mt][0], a[mt][1], a[mt][2], a[mt][3],
                        a_base[mt] + koff);
            uint32_t b[8][2];
            #pragma unroll
            for (int g = 0; g < 4; ++g)
                ldsm_x4(b[2 * g][0], b[2 * g][1],
                        b[2 * g + 1][0], b[2 * g + 1][1], b_base[g] + koff);
            #pragma unroll
            for (int nt = 0; nt < 8; ++nt) {
                #pragma unroll
                for (int mt = 0; mt < 2; ++mt) {
                    asm volatile(
                        "mma.sync.aligned.m16n8k16.row.col.f32.f16.f16.f32 "
                        "{%0,%1,%2,%3}, {%4,%5,%6,%7}, {%8,%9}, {%0,%1,%2,%3};"
                        : "+f"(acc[mt][nt][0]), "+f"(acc[mt][nt][1]),
                          "+f"(acc[mt][nt][2]), "+f"(acc[mt][nt][3])
                        : "r"(a[mt][0]), "r"(a[mt][1]),
                          "r"(a[mt][2]), "r"(a[mt][3]),
                          "r"(b[nt][0]), "r"(b[nt][1]));
                }
            }
        }
    }

    // Epilogue: fp16 half2 stores
    const int grp = lane >> 2;
    const int tig = lane & 3;
    const int rbase = wm * 32 + grp;
    #pragma unroll
    for (int mt = 0; mt < 2; ++mt) {
        int r0 = m0 + rbase + mt * 16;
        #pragma unroll
        for (int nt = 0; nt < 8; ++nt) {
            int cc = n0 + wn * 64 + nt * 8 + tig * 2;
            if (r0 < M) {
                __half2 h = __floats2half2_rn(acc[mt][nt][0], acc[mt][nt][1]);
                *reinterpret_cast<__half2*>(g_Yh + (size_t)r0 * NCOLS + cc) = h;
            }
            if (r0 + 8 < M) {
                __half2 h = __floats2half2_rn(acc[mt][nt][2], acc[mt][nt][3]);
                *reinterpret_cast<__half2*>(g_Yh + (size_t)(r0 + 8) * NCOLS + cc) = h;
            }
        }
    }
}

// ---------------------------------------------------------------------------
// Kernel 3: per edge e, out[e,:16] = tanh(Ysrc[src,t,:] + Ydst[dst,t,:])
// ONE thread per edge: 3 index loads + 4 independent 16 B gathers (MLP,
// Y fp16 L2-resident), 16 MUFU tanh.approx, 64 B coalesced output.
// Index-dtype detect fused per block (edge_types in 0..11: if int64 LE,
// every odd int32 word is 0; false-positive prob on int32 data (1/12)^256).
// ---------------------------------------------------------------------------
__global__ void edge_kernel(const void* __restrict__ ei,
                            const void* __restrict__ et,
                            float* __restrict__ out, int E) {
    const int* etw = (const int*)et;
    int probe = etw[2 * threadIdx.x + 1];
    int idx64 = !__syncthreads_or(probe != 0);

    int e = blockIdx.x * blockDim.x + threadIdx.x;
    if (e >= E) return;

    int src, dst, t;
    if (idx64) {
        const long long* ei64 = (const long long*)ei;
        const long long* et64 = (const long long*)et;
        src = (int)ei64[e];
        dst = (int)ei64[(size_t)E + e];
        t   = (int)et64[e];
    } else {
        const int* ei32 = (const int*)ei;
        src = ei32[e];
        dst = ei32[(size_t)E + e];
        t   = etw[e];
    }

    const __half* pa = g_Yh + (size_t)src * NCOLS + t * 16;
    const __half* pb = g_Yh + (size_t)dst * NCOLS + 192 + t * 16;
    uint4 va0 = *reinterpret_cast<const uint4*>(pa);
    uint4 va1 = *reinterpret_cast<const uint4*>(pa + 8);
    uint4 vb0 = *reinterpret_cast<const uint4*>(pb);
    uint4 vb1 = *reinterpret_cast<const uint4*>(pb + 8);

    const __half2* a0 = reinterpret_cast<const __half2*>(&va0);
    const __half2* a1 = reinterpret_cast<const __half2*>(&va1);
    const __half2* b0 = reinterpret_cast<const __half2*>(&vb0);
    const __half2* b1 = reinterpret_cast<const __half2*>(&vb1);

    float r[16];
    #pragma unroll
    for (int i = 0; i < 4; ++i) {
        float2 fa = __half22float2(a0[i]);
        float2 fb = __half22float2(b0[i]);
        r[2 * i]     = fast_tanh(fa.x + fb.x);
        r[2 * i + 1] = fast_tanh(fa.y + fb.y);
        float2 ga = __half22float2(a1[i]);
        float2 gb = __half22float2(b1[i]);
        r[8 + 2 * i]     = fast_tanh(ga.x + gb.x);
        r[8 + 2 * i + 1] = fast_tanh(ga.y + gb.y);
    }
    float* o = out + (size_t)e * 16;
    *reinterpret_cast<float4*>(o)      = make_float4(r[0],  r[1],  r[2],  r[3]);
    *reinterpret_cast<float4*>(o + 4)  = make_float4(r[4],  r[5],  r[6],  r[7]);
    *reinterpret_cast<float4*>(o + 8)  = make_float4(r[8],  r[9],  r[10], r[11]);
    *reinterpret_cast<float4*>(o + 12) = make_float4(r[12], r[13], r[14], r[15]);
}

// ---------------------------------------------------------------------------
extern "C" void kernel_launch(void* const* d_in, const int* in_sizes, int n_in,
                              void* d_out, int out_size) {
    const float* x  = (const float*)d_in[0];      // [N,128] f32
    const void*  ei = d_in[1];                    // [2,E] int32 or int64
    const void*  et = d_in[2];                    // [E]   int32 or int64
    const float* W  = (const float*)d_in[3];      // [12,256,16] f32

    const int N = in_sizes[0] / CDIM;
    const int E = in_sizes[2];

    // 1) Weight rearrange/transpose to fp16
    prep_kernel<<<192, 256>>>(W);

    // 2) Dense node-side GEMM: Y = X @ B (fp16 in/out, fp32 accumulate),
    //    K-pipelined double-buffered (static 40 KB smem)
    dim3 grid((N + 127) / 128, NCOLS / 128);
    gemm_kernel<<<grid, 256>>>(x, N);

    // 3) Edge gather + add + tanh, 1 thread/edge
    edge_kernel<<<(E + 255) / 256, 256>>>(ei, et, (float*)d_out, E);
}

// round 13
// speedup vs baseline: 1.0006x; 1.0006x over previous
#include <cuda_runtime.h>
#include <cuda_fp16.h>
#include <cstdint>

// Problem constants (fixed by the dataset):
//   N = 50000 nodes, C = 128 channels, E = 400000 edges,
//   T = 12 edge types, P = 16 (4x4 restriction map)
// Y layout per node: [half(src=0/dst=1)][t][p]  -> 2*12*16 = 384 cols
#define NMAX   50000
#define CDIM   128
#define NCOLS  384

// Scratch (allocation-free rule: __device__ globals)
__device__ __half g_Yh[(size_t)NMAX * NCOLS];        // 38.4 MB, fp16 node partials

__device__ __forceinline__ uint32_t smem_u32(const void* p) {
    return (uint32_t)__cvta_generic_to_shared(p);
}
__device__ __forceinline__ void ldsm_x4(uint32_t& r0, uint32_t& r1,
                                        uint32_t& r2, uint32_t& r3,
                                        uint32_t addr) {
    asm volatile("ldmatrix.sync.aligned.m8n8.x4.shared.b16 {%0,%1,%2,%3}, [%4];"
                 : "=r"(r0), "=r"(r1), "=r"(r2), "=r"(r3) : "r"(addr));
}
__device__ __forceinline__ float fast_tanh(float x) {
    float y;
    asm("tanh.approx.f32 %0, %1;" : "=f"(y) : "f"(x));
    return y;
}

// ---------------------------------------------------------------------------
// Kernel 1: Y[M,384] = fp16(X[M,128]) @ B^T, fp32 accumulate, fp16 out,
// with the weight rearrangement FUSED into the B-tile load (no prep kernel).
//
// B tile for n-block n0: n = g*16 + p where g = half*12 + t; the 128 n-values
// [n0, n0+128) correspond to g = n0/16 + b, b in 0..7, i.e. 8 contiguous
// 2048-float blocks of W at base (t*256 + half*128)*16 (t = g%12, half=g/12).
// Thread loads are coalesced float4 from W; stores are 4 scattered STS.16
// into the k-major Bs tile (conflicts hidden under the co-resident CTA).
//
// CTA tile 128(M) x 128(N), FULL K=128 resident in smem, single sync.
// 256 threads = 8 warps in 4(M) x 2(N); warp tile 32x64 via
// ldmatrix.x4 + mma.m16n8k16.f16 (fp32 accumulate).
// Smem rows padded to 136 halves (272 B): LDSM 8-row phases conflict-free.
// ---------------------------------------------------------------------------
#define SPAD      136
#define AS_ELEMS  (128 * SPAD)
#define GEMM_SMEM_BYTES (2 * AS_ELEMS * 2)   // 69632 B (dynamic, opt-in)

__global__ void __launch_bounds__(256, 2)
gemm_kernel(const float* __restrict__ X, const float* __restrict__ W, int M) {
    extern __shared__ __half smem[];
    __half* As = smem;              // [128][SPAD]  rows = m, cols = k
    __half* Bs = smem + AS_ELEMS;   // [128][SPAD]  rows = n_local, cols = k

    const int m0  = blockIdx.x * 128;
    const int n0  = blockIdx.y * 128;
    const int tid = threadIdx.x;

    // ---- B tile: coalesced float4 from W, fused permute + fp16 cvt ----
    #pragma unroll
    for (int i = 0; i < 16; ++i) {
        int j   = (tid + i * 256) * 4;    // float index in the 16K-float slice
        int b   = j >> 11;                // block 0..7 (2048 floats each)
        int rem = j & 2047;               // k*16 + p
        int k   = rem >> 4;
        int p   = rem & 15;               // p, p+1, p+2, p+3 in this float4
        int g   = (n0 >> 4) + b;          // = half*12 + t
        int hf  = (g >= 12);
        int t   = g - hf * 12;
        const float* src = W + (((size_t)(t * 256 + hf * 128)) << 4) + rem;
        float4 v = *reinterpret_cast<const float4*>(src);
        int nl = b * 16 + p;              // n_local = n - n0
        Bs[(nl + 0) * SPAD + k] = __float2half_rn(v.x);
        Bs[(nl + 1) * SPAD + k] = __float2half_rn(v.y);
        Bs[(nl + 2) * SPAD + k] = __float2half_rn(v.z);
        Bs[(nl + 3) * SPAD + k] = __float2half_rn(v.w);
    }

    // ---- A tile: LDG f32x4 -> cvt fp16 -> STS 8 B ----
    #pragma unroll
    for (int i = 0; i < 16; ++i) {
        int li = tid + i * 256;          // 0..4095
        int r  = li >> 5;                // m row 0..127
        int c  = (li & 31) << 2;         // k col (f32 granularity)
        float4 v = make_float4(0.f, 0.f, 0.f, 0.f);
        if (m0 + r < M)
            v = *reinterpret_cast<const float4*>(X + (size_t)(m0 + r) * CDIM + c);
        __half2 h0 = __floats2half2_rn(v.x, v.y);
        __half2 h1 = __floats2half2_rn(v.z, v.w);
        *reinterpret_cast<__half2*>(As + r * SPAD + c)     = h0;
        *reinterpret_cast<__half2*>(As + r * SPAD + c + 2) = h1;
    }
    __syncthreads();

    const int warp = tid >> 5;
    const int lane = tid & 31;
    const int wm   = warp >> 1;   // 0..3
    const int wn   = warp & 1;    // 0..1

    float acc[2][8][4];
    #pragma unroll
    for (int mt = 0; mt < 2; ++mt)
        #pragma unroll
        for (int nt = 0; nt < 8; ++nt)
            #pragma unroll
            for (int q = 0; q < 4; ++q)
                acc[mt][nt][q] = 0.f;

    // ldmatrix base addresses (k0 = 0); advance 32 B per k16 step.
    const int mat = lane >> 3;
    const int mrl = lane & 7;
    uint32_t a_addr[2];
    #pragma unroll
    for (int mt = 0; mt < 2; ++mt) {
        int row = wm * 32 + mt * 16 + (mat & 1) * 8 + mrl;
        int col = (mat >> 1) * 8;
        a_addr[mt] = smem_u32(As + row * SPAD + col);
    }
    uint32_t b_addr[4];
    #pragma unroll
    for (int g = 0; g < 4; ++g) {
        int row = wn * 64 + (2 * g + (mat >> 1)) * 8 + mrl;
        int col = (mat & 1) * 8;
        b_addr[g] = smem_u32(Bs + row * SPAD + col);
    }

    #pragma unroll
    for (int ks = 0; ks < CDIM / 16; ++ks) {  // 8 k16 steps
        const uint32_t koff = ks * 32;        // 16 halves = 32 B
        uint32_t a[2][4];
        #pragma unroll
        for (int mt = 0; mt < 2; ++mt)
            ldsm_x4(a[mt][0], a[mt][1], a[mt][2], a[mt][3], a_addr[mt] + koff);
        uint32_t b[8][2];
        #pragma unroll
        for (int g = 0; g < 4; ++g)
            ldsm_x4(b[2 * g][0], b[2 * g][1], b[2 * g + 1][0], b[2 * g + 1][1],
                    b_addr[g] + koff);
        #pragma unroll
        for (int nt = 0; nt < 8; ++nt) {
            #pragma unroll
            for (int mt = 0; mt < 2; ++mt) {
                asm volatile(
                    "mma.sync.aligned.m16n8k16.row.col.f32.f16.f16.f32 "
                    "{%0,%1,%2,%3}, {%4,%5,%6,%7}, {%8,%9}, {%0,%1,%2,%3};"
                    : "+f"(acc[mt][nt][0]), "+f"(acc[mt][nt][1]),
                      "+f"(acc[mt][nt][2]), "+f"(acc[mt][nt][3])
                    : "r"(a[mt][0]), "r"(a[mt][1]), "r"(a[mt][2]), "r"(a[mt][3]),
                      "r"(b[nt][0]), "r"(b[nt][1]));
            }
        }
    }

    // Epilogue: fp16 half2 stores
    const int grp = lane >> 2;
    const int tig = lane & 3;
    const int rbase = wm * 32 + grp;
    #pragma unroll
    for (int mt = 0; mt < 2; ++mt) {
        int r0 = m0 + rbase + mt * 16;
        #pragma unroll
        for (int nt = 0; nt < 8; ++nt) {
            int cc = n0 + wn * 64 + nt * 8 + tig * 2;
            if (r0 < M) {
                __half2 h = __floats2half2_rn(acc[mt][nt][0], acc[mt][nt][1]);
                *reinterpret_cast<__half2*>(g_Yh + (size_t)r0 * NCOLS + cc) = h;
            }
            if (r0 + 8 < M) {
                __half2 h = __floats2half2_rn(acc[mt][nt][2], acc[mt][nt][3]);
                *reinterpret_cast<__half2*>(g_Yh + (size_t)(r0 + 8) * NCOLS + cc) = h;
            }
        }
    }
}

// ---------------------------------------------------------------------------
// Kernel 2: per edge e, out[e,:16] = tanh(Ysrc[src,t,:] + Ydst[dst,t,:])
// ONE thread per edge: 3 index loads + 4 independent 16 B gathers (MLP,
// Y fp16 L2-resident), 16 MUFU tanh.approx, 64 B coalesced output.
// Index-dtype detect fused per block (edge_types in 0..11: if int64 LE,
// every odd int32 word is 0; false-positive prob on int32 data (1/12)^256).
// ---------------------------------------------------------------------------
__global__ void edge_kernel(const void* __restrict__ ei,
                            const void* __restrict__ et,
                            float* __restrict__ out, int E) {
    const int* etw = (const int*)et;
    int probe = etw[2 * threadIdx.x + 1];
    int idx64 = !__syncthreads_or(probe != 0);

    int e = blockIdx.x * blockDim.x + threadIdx.x;
    if (e >= E) return;

    int src, dst, t;
    if (idx64) {
        const long long* ei64 = (const long long*)ei;
        const long long* et64 = (const long long*)et;
        src = (int)ei64[e];
        dst = (int)ei64[(size_t)E + e];
        t   = (int)et64[e];
    } else {
        const int* ei32 = (const int*)ei;
        src = ei32[e];
        dst = ei32[(size_t)E + e];
        t   = etw[e];
    }

    const __half* pa = g_Yh + (size_t)src * NCOLS + t * 16;
    const __half* pb = g_Yh + (size_t)dst * NCOLS + 192 + t * 16;
    uint4 va0 = *reinterpret_cast<const uint4*>(pa);
    uint4 va1 = *reinterpret_cast<const uint4*>(pa + 8);
    uint4 vb0 = *reinterpret_cast<const uint4*>(pb);
    uint4 vb1 = *reinterpret_cast<const uint4*>(pb + 8);

    const __half2* a0 = reinterpret_cast<const __half2*>(&va0);
    const __half2* a1 = reinterpret_cast<const __half2*>(&va1);
    const __half2* b0 = reinterpret_cast<const __half2*>(&vb0);
    const __half2* b1 = reinterpret_cast<const __half2*>(&vb1);

    float r[16];
    #pragma unroll
    for (int i = 0; i < 4; ++i) {
        float2 fa = __half22float2(a0[i]);
        float2 fb = __half22float2(b0[i]);
        r[2 * i]     = fast_tanh(fa.x + fb.x);
        r[2 * i + 1] = fast_tanh(fa.y + fb.y);
        float2 ga = __half22float2(a1[i]);
        float2 gb = __half22float2(b1[i]);
        r[8 + 2 * i]     = fast_tanh(ga.x + gb.x);
        r[8 + 2 * i + 1] = fast_tanh(ga.y + gb.y);
    }
    float* o = out + (size_t)e * 16;
    *reinterpret_cast<float4*>(o)      = make_float4(r[0],  r[1],  r[2],  r[3]);
    *reinterpret_cast<float4*>(o + 4)  = make_float4(r[4],  r[5],  r[6],  r[7]);
    *reinterpret_cast<float4*>(o + 8)  = make_float4(r[8],  r[9],  r[10], r[11]);
    *reinterpret_cast<float4*>(o + 12) = make_float4(r[12], r[13], r[14], r[15]);
}

// ---------------------------------------------------------------------------
extern "C" void kernel_launch(void* const* d_in, const int* in_sizes, int n_in,
                              void* d_out, int out_size) {
    const float* x  = (const float*)d_in[0];      // [N,128] f32
    const void*  ei = d_in[1];                    // [2,E] int32 or int64
    const void*  et = d_in[2];                    // [E]   int32 or int64
    const float* W  = (const float*)d_in[3];      // [12,256,16] f32

    const int N = in_sizes[0] / CDIM;
    const int E = in_sizes[2];

    // Opt-in >48 KB dynamic smem (immediate host attr set; capture-legal,
    // unconditional -> deterministic).
    cudaFuncSetAttribute(gemm_kernel,
                         cudaFuncAttributeMaxDynamicSharedMemorySize,
                         GEMM_SMEM_BYTES);

    // 1) Dense node-side GEMM with fused weight permute: Y = X @ B
    dim3 grid((N + 127) / 128, NCOLS / 128);
    gemm_kernel<<<grid, 256, GEMM_SMEM_BYTES>>>(x, W, N);

    // 2) Edge gather + add + tanh, 1 thread/edge
    edge_kernel<<<(E + 255) / 256, 256>>>(ei, et, (float*)d_out, E);
}

// round 14
// speedup vs baseline: 1.0826x; 1.0820x over previous
#include <cuda_runtime.h>
#include <cuda_fp16.h>
#include <cstdint>

// Problem constants (fixed by the dataset):
//   N = 50000 nodes, C = 128 channels, E = 400000 edges,
//   T = 12 edge types, P = 16 (4x4 restriction map)
// Y layout per node: [half(src=0/dst=1)][t][p]  -> 2*12*16 = 384 cols
#define NMAX   50000
#define CDIM   128
#define NCOLS  384

// Scratch (allocation-free rule: __device__ globals)
__device__ __half g_Bh[NCOLS * CDIM];                // 96 KB, fp16 W^T: [n][k]
__device__ __half g_Yh[(size_t)NMAX * NCOLS];        // 38.4 MB, fp16 node partials

__device__ __forceinline__ uint32_t smem_u32(const void* p) {
    return (uint32_t)__cvta_generic_to_shared(p);
}
__device__ __forceinline__ void cp_async16(void* smem_dst, const void* gsrc) {
    asm volatile("cp.async.ca.shared.global [%0], [%1], 16;\n"
                 :: "r"(smem_u32(smem_dst)), "l"(gsrc));
}
#define CP_COMMIT() asm volatile("cp.async.commit_group;\n" ::)
#define CP_WAIT0()  asm volatile("cp.async.wait_group 0;\n" ::)

__device__ __forceinline__ void ldsm_x4(uint32_t& r0, uint32_t& r1,
                                        uint32_t& r2, uint32_t& r3,
                                        uint32_t addr) {
    asm volatile("ldmatrix.sync.aligned.m8n8.x4.shared.b16 {%0,%1,%2,%3}, [%4];"
                 : "=r"(r0), "=r"(r1), "=r"(r2), "=r"(r3) : "r"(addr));
}
__device__ __forceinline__ float fast_tanh(float x) {
    float y;
    asm("tanh.approx.f32 %0, %1;" : "=f"(y) : "f"(x));
    return y;
}

// ---------------------------------------------------------------------------
// Kernel 1: prep — coalesced read of W, scattered fp16 write to global.
// Thread i reads W[i]; i = ((t*256 + row)*16 + p), row = half*128 + c;
// writes g_Bh[n*128 + c] with n = half*192 + t*16 + p.
// ---------------------------------------------------------------------------
__global__ void prep_kernel(const float* __restrict__ W) {
    int i = blockIdx.x * blockDim.x + threadIdx.x;   // 0 .. 49151
    float w = W[i];
    int p   = i & 15;
    int row = (i >> 4) & 255;
    int t   = i >> 12;
    int half = row >> 7;
    int c    = row & 127;
    int n    = half * 192 + t * 16 + p;
    g_Bh[n * CDIM + c] = __float2half_rn(w);
}

// ---------------------------------------------------------------------------
// Kernel 2: Y[M,384] = fp16(X[M,128]) @ Bh^T, fp32 accumulate, fp16 out.
// Grid (ceil(M/128), 1): each CTA loads its A tile (128x128) ONCE, then
// loops the 3 n-blocks of 128, loading each B tile from g_Bh (L2-resident)
// and reusing the same acc registers. X DRAM traffic drops 3x vs the
// (391,3) grid (115 MB -> ~64 MB total GEMM traffic).
// 256 threads = 8 warps in 4(M) x 2(N); warp tile 32x64 via
// ldmatrix.x4 + mma.m16n8k16.f16. SPAD=136 -> conflict-free LDSM phases.
// ---------------------------------------------------------------------------
#define SPAD      136
#define AS_ELEMS  (128 * SPAD)
#define GEMM_SMEM_BYTES (2 * AS_ELEMS * 2)   // 69632 B (dynamic, opt-in)

__global__ void __launch_bounds__(256, 2)
gemm_kernel(const float* __restrict__ X, int M) {
    extern __shared__ __half smem[];
    __half* As = smem;              // [128][SPAD]  rows = m, cols = k
    __half* Bs = smem + AS_ELEMS;   // [128][SPAD]  rows = n_local, cols = k

    const int m0  = blockIdx.x * 128;
    const int tid = threadIdx.x;

    // ---- A tile (once): LDG f32x4 -> cvt fp16 -> STS 8 B ----
    #pragma unroll
    for (int i = 0; i < 16; ++i) {
        int li = tid + i * 256;          // 0..4095
        int r  = li >> 5;                // m row 0..127
        int c  = (li & 31) << 2;         // k col (f32 granularity)
        float4 v = make_float4(0.f, 0.f, 0.f, 0.f);
        if (m0 + r < M)
            v = *reinterpret_cast<const float4*>(X + (size_t)(m0 + r) * CDIM + c);
        __half2 h0 = __floats2half2_rn(v.x, v.y);
        __half2 h1 = __floats2half2_rn(v.z, v.w);
        *reinterpret_cast<__half2*>(As + r * SPAD + c)     = h0;
        *reinterpret_cast<__half2*>(As + r * SPAD + c + 2) = h1;
    }

    const int warp = tid >> 5;
    const int lane = tid & 31;
    const int wm   = warp >> 1;   // 0..3
    const int wn   = warp & 1;    // 0..1
    const int mat  = lane >> 3;
    const int mrl  = lane & 7;

    // ldmatrix base addresses (k0 = 0); advance 32 B per k16 step.
    uint32_t a_addr[2];
    #pragma unroll
    for (int mt = 0; mt < 2; ++mt) {
        int row = wm * 32 + mt * 16 + (mat & 1) * 8 + mrl;
        int col = (mat >> 1) * 8;
        a_addr[mt] = smem_u32(As + row * SPAD + col);
    }
    uint32_t b_addr[4];
    #pragma unroll
    for (int g = 0; g < 4; ++g) {
        int row = wn * 64 + (2 * g + (mat >> 1)) * 8 + mrl;
        int col = (mat & 1) * 8;
        b_addr[g] = smem_u32(Bs + row * SPAD + col);
    }

    const int grp   = lane >> 2;
    const int tig   = lane & 3;
    const int rbase = wm * 32 + grp;

    // ---- Loop over the 3 n-blocks, reusing A and acc registers ----
    for (int nb = 0; nb < 3; ++nb) {
        const int n0 = nb * 128;

        // B tile: straight fp16 row copy via cp.async (L2-resident source)
        #pragma unroll
        for (int i = 0; i < 8; ++i) {
            int li = tid + i * 256;          // 0..2047
            int r  = li >> 4;                // n_local 0..127
            int c  = (li & 15) << 3;         // k chunk start (8 halves)
            cp_async16(Bs + r * SPAD + c, g_Bh + (size_t)(n0 + r) * CDIM + c);
        }
        CP_COMMIT();
        CP_WAIT0();
        __syncthreads();                     // B (and, on nb=0, A) visible

        float acc[2][8][4];
        #pragma unroll
        for (int mt = 0; mt < 2; ++mt)
            #pragma unroll
            for (int nt = 0; nt < 8; ++nt)
                #pragma unroll
                for (int q = 0; q < 4; ++q)
                    acc[mt][nt][q] = 0.f;

        #pragma unroll
        for (int ks = 0; ks < CDIM / 16; ++ks) {  // 8 k16 steps
            const uint32_t koff = ks * 32;        // 16 halves = 32 B
            uint32_t a[2][4];
            #pragma unroll
            for (int mt = 0; mt < 2; ++mt)
                ldsm_x4(a[mt][0], a[mt][1], a[mt][2], a[mt][3],
                        a_addr[mt] + koff);
            uint32_t b[8][2];
            #pragma unroll
            for (int g = 0; g < 4; ++g)
                ldsm_x4(b[2 * g][0], b[2 * g][1],
                        b[2 * g + 1][0], b[2 * g + 1][1], b_addr[g] + koff);
            #pragma unroll
            for (int nt = 0; nt < 8; ++nt) {
                #pragma unroll
                for (int mt = 0; mt < 2; ++mt) {
                    asm volatile(
                        "mma.sync.aligned.m16n8k16.row.col.f32.f16.f16.f32 "
                        "{%0,%1,%2,%3}, {%4,%5,%6,%7}, {%8,%9}, {%0,%1,%2,%3};"
                        : "+f"(acc[mt][nt][0]), "+f"(acc[mt][nt][1]),
                          "+f"(acc[mt][nt][2]), "+f"(acc[mt][nt][3])
                        : "r"(a[mt][0]), "r"(a[mt][1]),
                          "r"(a[mt][2]), "r"(a[mt][3]),
                          "r"(b[nt][0]), "r"(b[nt][1]));
                }
            }
        }

        // Epilogue for this n-block: fp16 half2 stores
        #pragma unroll
        for (int mt = 0; mt < 2; ++mt) {
            int r0 = m0 + rbase + mt * 16;
            #pragma unroll
            for (int nt = 0; nt < 8; ++nt) {
                int cc = n0 + wn * 64 + nt * 8 + tig * 2;
                if (r0 < M) {
                    __half2 h = __floats2half2_rn(acc[mt][nt][0], acc[mt][nt][1]);
                    *reinterpret_cast<__half2*>(g_Yh + (size_t)r0 * NCOLS + cc) = h;
                }
                if (r0 + 8 < M) {
                    __half2 h = __floats2half2_rn(acc[mt][nt][2], acc[mt][nt][3]);
                    *reinterpret_cast<__half2*>(g_Yh + (size_t)(r0 + 8) * NCOLS + cc) = h;
                }
            }
        }
        __syncthreads();   // all warps done reading Bs before next cp.async
    }
}

// ---------------------------------------------------------------------------
// Kernel 3: per edge e, out[e,:16] = tanh(Ysrc[src,t,:] + Ydst[dst,t,:])
// ONE thread per edge: 3 index loads + 4 independent 16 B gathers (MLP,
// Y fp16 L2-resident), 16 MUFU tanh.approx, 64 B coalesced output.
// Index-dtype detect fused per block (edge_types in 0..11: if int64 LE,
// every odd int32 word is 0; false-positive prob on int32 data (1/12)^256).
// ---------------------------------------------------------------------------
__global__ void edge_kernel(const void* __restrict__ ei,
                            const void* __restrict__ et,
                            float* __restrict__ out, int E) {
    const int* etw = (const int*)et;
    int probe = etw[2 * threadIdx.x + 1];
    int idx64 = !__syncthreads_or(probe != 0);

    int e = blockIdx.x * blockDim.x + threadIdx.x;
    if (e >= E) return;

    int src, dst, t;
    if (idx64) {
        const long long* ei64 = (const long long*)ei;
        const long long* et64 = (const long long*)et;
        src = (int)ei64[e];
        dst = (int)ei64[(size_t)E + e];
        t   = (int)et64[e];
    } else {
        const int* ei32 = (const int*)ei;
        src = ei32[e];
        dst = ei32[(size_t)E + e];
        t   = etw[e];
    }

    const __half* pa = g_Yh + (size_t)src * NCOLS + t * 16;
    const __half* pb = g_Yh + (size_t)dst * NCOLS + 192 + t * 16;
    uint4 va0 = *reinterpret_cast<const uint4*>(pa);
    uint4 va1 = *reinterpret_cast<const uint4*>(pa + 8);
    uint4 vb0 = *reinterpret_cast<const uint4*>(pb);
    uint4 vb1 = *reinterpret_cast<const uint4*>(pb + 8);

    const __half2* a0 = reinterpret_cast<const __half2*>(&va0);
    const __half2* a1 = reinterpret_cast<const __half2*>(&va1);
    const __half2* b0 = reinterpret_cast<const __half2*>(&vb0);
    const __half2* b1 = reinterpret_cast<const __half2*>(&vb1);

    float r[16];
    #pragma unroll
    for (int i = 0; i < 4; ++i) {
        float2 fa = __half22float2(a0[i]);
        float2 fb = __half22float2(b0[i]);
        r[2 * i]     = fast_tanh(fa.x + fb.x);
        r[2 * i + 1] = fast_tanh(fa.y + fb.y);
        float2 ga = __half22float2(a1[i]);
        float2 gb = __half22float2(b1[i]);
        r[8 + 2 * i]     = fast_tanh(ga.x + gb.x);
        r[8 + 2 * i + 1] = fast_tanh(ga.y + gb.y);
    }
    float* o = out + (size_t)e * 16;
    *reinterpret_cast<float4*>(o)      = make_float4(r[0],  r[1],  r[2],  r[3]);
    *reinterpret_cast<float4*>(o + 4)  = make_float4(r[4],  r[5],  r[6],  r[7]);
    *reinterpret_cast<float4*>(o + 8)  = make_float4(r[8],  r[9],  r[10], r[11]);
    *reinterpret_cast<float4*>(o + 12) = make_float4(r[12], r[13], r[14], r[15]);
}

// ---------------------------------------------------------------------------
extern "C" void kernel_launch(void* const* d_in, const int* in_sizes, int n_in,
                              void* d_out, int out_size) {
    const float* x  = (const float*)d_in[0];      // [N,128] f32
    const void*  ei = d_in[1];                    // [2,E] int32 or int64
    const void*  et = d_in[2];                    // [E]   int32 or int64
    const float* W  = (const float*)d_in[3];      // [12,256,16] f32

    const int N = in_sizes[0] / CDIM;
    const int E = in_sizes[2];

    // Opt-in >48 KB dynamic smem (immediate host attr set; capture-legal,
    // unconditional -> deterministic).
    cudaFuncSetAttribute(gemm_kernel,
                         cudaFuncAttributeMaxDynamicSharedMemorySize,
                         GEMM_SMEM_BYTES);

    // 1) Weight rearrange/transpose to fp16
    prep_kernel<<<192, 256>>>(W);

    // 2) Dense node-side GEMM: A loaded once, 3 n-blocks looped in-CTA
    dim3 grid((N + 127) / 128, 1);
    gemm_kernel<<<grid, 256, GEMM_SMEM_BYTES>>>(x, N);

    // 3) Edge gather + add + tanh, 1 thread/edge
    edge_kernel<<<(E + 255) / 256, 256>>>(ei, et, (float*)d_out, E);
}